// round 13
// baseline (speedup 1.0000x reference)
#include <cuda_runtime.h>
#include <cuda_bf16.h>
#include <cstdint>

// DLRM dot-interaction via BF16 tensor cores, 3-term split, persistent CTAs with
// cp.async double-buffered prefetch. One sample at a time per 64-thread CTA
// (2 warps, split-k 64 dims each); while computing buffer b, the next sample is
// prefetched into b^1 with cp.async.cg (async, waits deferred to wait_group).
// Grid = 888 (6 CTAs/SM x 148), each CTA loops ~18 samples.

constexpr int Bt      = 16384;
constexpr int NE      = 26;
constexpr int D       = 128;
constexpr int N       = 27;
constexpr int NPAIR   = N * (N - 1) / 2;   // 351
constexpr int STRF    = 136;               // floats per smem row
constexpr int STR4    = 34;                // float4 per smem row
constexpr int NTHR    = 64;
constexpr int NTILE   = 6;
constexpr int GRID    = 888;               // 6 resident CTAs x 148 SMs

__device__ __forceinline__ void mma_bf16(float* c,
    uint32_t a0, uint32_t a1, uint32_t a2, uint32_t a3,
    uint32_t b0, uint32_t b1)
{
    asm volatile(
        "mma.sync.aligned.m16n8k16.row.col.f32.bf16.bf16.f32 "
        "{%0,%1,%2,%3}, {%4,%5,%6,%7}, {%8,%9}, {%0,%1,%2,%3};"
        : "+f"(c[0]), "+f"(c[1]), "+f"(c[2]), "+f"(c[3])
        : "r"(a0), "r"(a1), "r"(a2), "r"(a3), "r"(b0), "r"(b1));
}

__device__ __forceinline__ void split2(float2 v, uint32_t& hi, uint32_t& lo)
{
    const uint32_t bx = __float_as_uint(v.x), by = __float_as_uint(v.y);
    hi = __byte_perm(bx, by, 0x7632);        // low16 = v.x_hi, high16 = v.y_hi
    const float lx = v.x - __uint_as_float(bx & 0xFFFF0000u);
    const float ly = v.y - __uint_as_float(by & 0xFFFF0000u);
    __nv_bfloat162 l2 = __floats2bfloat162_rn(lx, ly);
    lo = *reinterpret_cast<uint32_t*>(&l2);
}

__device__ __forceinline__ void cp16(uint32_t dst, const void* src)
{
    asm volatile("cp.async.cg.shared.global [%0], [%1], 16;" :: "r"(dst), "l"(src));
}

__global__ void __launch_bounds__(NTHR)
dot_interaction_kernel(const float* __restrict__ dense,
                       const float* __restrict__ embs,
                       float* __restrict__ out)
{
    __shared__ float S[2][32 * STRF];                // 2 x 17408 B = 34816 B

    const int tid  = threadIdx.x;
    const int kw   = tid >> 5;
    const int lane = tid & 31;
    const int g    = lane >> 2;
    const int t4   = lane & 3;

    uint32_t sb[2];
    sb[0] = (uint32_t)__cvta_generic_to_shared(&S[0][0]);
    sb[1] = (uint32_t)__cvta_generic_to_shared(&S[1][0]);

    // Prefetch issuer: dense row -> row 0, embs rows -> rows 1..26 (f4 granularity)
    auto issue = [&](int s, int b) {
        const float4* d4 = reinterpret_cast<const float4*>(dense + (size_t)s * D);
        const float4* e4 = reinterpret_cast<const float4*>(embs + (size_t)s * NE * D);
        if (tid < 32) cp16(sb[b] + tid * 16, d4 + tid);
        #pragma unroll
        for (int i = 0; i < 13; i++) {               // 832 f4 over 64 threads
            const int idx = tid + i * NTHR;
            const int row = (idx >> 5) + 1, col = idx & 31;
            cp16(sb[b] + (row * STR4 + col) * 16, e4 + idx);
        }
        asm volatile("cp.async.commit_group;");
    };

    const int stride = gridDim.x;
    int s = blockIdx.x;
    if (s < Bt) issue(s, 0);

    // Zero pad rows 27..31 of both buffers once (prefetch/reduction never touch them)
    #pragma unroll
    for (int b = 0; b < 2; b++)
        for (int i = tid; i < 5 * 32; i += NTHR) {
            const int row = 27 + (i >> 5), col = i & 31;
            reinterpret_cast<float4*>(&S[b][0])[row * STR4 + col] =
                make_float4(0.f, 0.f, 0.f, 0.f);
        }

    constexpr int MT[NTILE] = {0, 0, 0, 0, 1, 1};
    constexpr int NT[NTILE] = {0, 1, 2, 3, 2, 3};

    int buf = 0;
    for (; s < Bt; s += stride) {
        const int snext = s + stride;
        if (snext < Bt) {
            issue(snext, buf ^ 1);
            asm volatile("cp.async.wait_group 1;");  // current buffer complete
        } else {
            asm volatile("cp.async.wait_group 0;");
        }
        __syncthreads();

        float* Sb = &S[buf][0];

        float acc[NTILE][4];
        #pragma unroll
        for (int e = 0; e < NTILE; e++)
            #pragma unroll
            for (int c = 0; c < 4; c++) acc[e][c] = 0.f;

        const int kbase = kw * 64;
        #pragma unroll
        for (int kt = 0; kt < 4; kt++) {
            const int kc = kbase + kt * 16 + 2 * t4;

            uint32_t bh[4][2], bl[4][2];
            #pragma unroll
            for (int nt = 0; nt < 4; nt++) {
                const int n = nt * 8 + g;
                split2(*reinterpret_cast<const float2*>(&Sb[n * STRF + kc    ]), bh[nt][0], bl[nt][0]);
                split2(*reinterpret_cast<const float2*>(&Sb[n * STRF + kc + 8]), bh[nt][1], bl[nt][1]);
            }
            #pragma unroll
            for (int e = 0; e < NTILE; e++) {
                float* c = acc[e];
                const int m2 = 2 * MT[e], n = NT[e];
                mma_bf16(c, bl[m2][0], bl[m2+1][0], bl[m2][1], bl[m2+1][1],
                            bh[n][0],  bh[n][1]);
                mma_bf16(c, bh[m2][0], bh[m2+1][0], bh[m2][1], bh[m2+1][1],
                            bl[n][0],  bl[n][1]);
                mma_bf16(c, bh[m2][0], bh[m2+1][0], bh[m2][1], bh[m2+1][1],
                            bh[n][0],  bh[n][1]);
            }
        }

        // ---- Symmetric cross-warp exchange via dead tile smem (rows 0..5) ----
        __syncthreads();                             // all compute reads done
        if (kw == 1) {
            #pragma unroll
            for (int e = 0; e < 3; e++)              // region A: floats 0..383
                #pragma unroll
                for (int c = 0; c < 4; c++)
                    Sb[(e * 4 + c) * 32 + lane] = acc[e][c];
        } else {
            #pragma unroll
            for (int e = 3; e < 6; e++)              // region B: floats 384..767
                #pragma unroll
                for (int c = 0; c < 4; c++)
                    Sb[384 + ((e - 3) * 4 + c) * 32 + lane] = acc[e][c];
        }
        __syncthreads();

        {
            float* orow = out + (size_t)s * NPAIR;
            const int e0 = (kw == 0) ? 0 : 3;
            const int off = (kw == 0) ? 0 : 384;
            #pragma unroll
            for (int q = 0; q < 3; q++) {
                const int e = e0 + q;
                #pragma unroll
                for (int c = 0; c < 4; c++) {
                    const float v = acc[e][c] + Sb[off + (q * 4 + c) * 32 + lane];
                    const int i = MT[e] * 16 + g + ((c & 2) ? 8 : 0);
                    const int j = NT[e] * 8 + 2 * t4 + (c & 1);
                    if (i < j && j < N)
                        orow[i * (2 * N - 1 - i) / 2 + (j - i - 1)] = v;
                }
            }
        }
        __syncthreads();                             // epilogue reads done before
        buf ^= 1;                                    // next prefetch reuses Sb
    }
}

extern "C" void kernel_launch(void* const* d_in, const int* in_sizes, int n_in,
                              void* d_out, int out_size)
{
    const float* dense = (const float*)d_in[0];
    const float* embs  = (const float*)d_in[1];
    float* out = (float*)d_out;
    dot_interaction_kernel<<<GRID, NTHR>>>(dense, embs, out);
}